// round 8
// baseline (speedup 1.0000x reference)
#include <cuda_runtime.h>
#include <cuda_bf16.h>
#include <cstdint>
#include <cstddef>

// ---------------------------------------------------------------------------
// BatchChildSumTreeLSTM on GB300 — round 5: fused per-level kernel
//   EMBPROJ[50048,512] = emb @ [W_ix|W_ox|W_ux|W_fx] + combined bias (once)
//   per non-leaf level:
//     FH = h_child @ W_fh                       (gemm_mma, unchanged)
//     fused_level: hsum(on-the-fly) -> HG GEMM (Wh resident in smem)
//                  -> full LSTM gate math in-block (hg never hits DRAM)
//   leaf level: ew_kernel (gather EMBPROJ only)
//   Split precision everywhere: bf16 hi+lo, D = Ahi*Bhi + Ahi*Blo + Alo*Bhi.
// ---------------------------------------------------------------------------

#define N_NODES_C 741376
#define VOCAB_C 50000
#define VOCAB_PAD_C 50048   // multiple of 64

// ----------------------- static scratch (no allocs allowed) ----------------
__device__ float g_embproj[(size_t)VOCAB_PAD_C * 512];          // 102.5 MB
__device__ float g_fh[(size_t)262144 * 128];                    // 134 MB
__device__ __nv_bfloat16 g_h_hi0[(size_t)262144 * 128];
__device__ __nv_bfloat16 g_h_lo0[(size_t)262144 * 128];
__device__ __nv_bfloat16 g_h_hi1[(size_t)262144 * 128];
__device__ __nv_bfloat16 g_h_lo1[(size_t)262144 * 128];
__device__ float g_c0[(size_t)262144 * 128];
__device__ float g_c1[(size_t)262144 * 128];
__device__ __nv_bfloat16 g_emb_hi[(size_t)VOCAB_C * 128];
__device__ __nv_bfloat16 g_emb_lo[(size_t)VOCAB_C * 128];
__device__ __nv_bfloat16 g_wx_hi[512 * 128], g_wx_lo[512 * 128];  // [n][k]
__device__ __nv_bfloat16 g_wh_hi[384 * 128], g_wh_lo[384 * 128];
__device__ __nv_bfloat16 g_wf_hi[128 * 128], g_wf_lo[128 * 128];
__device__ float g_bias[512];

// ----------------------- helpers --------------------------------------------
__device__ __forceinline__ uint32_t smem_u32(const void* p) {
    uint32_t a;
    asm("{ .reg .u64 t; cvta.to.shared.u64 t, %1; cvt.u32.u64 %0, t; }" : "=r"(a) : "l"(p));
    return a;
}
__device__ __forceinline__ float sigf(float x) { return __fdividef(1.f, 1.f + __expf(-x)); }
__device__ __forceinline__ float tanh_(float x) {
    float a = fabsf(x);
    float e = __expf(-2.f * a);
    float t = (1.f - e) * __fdividef(1.f, 1.f + e);
    return copysignf(t, x);
}
__device__ __forceinline__ void split2(float v, __nv_bfloat16& hi, __nv_bfloat16& lo) {
    hi = __float2bfloat16(v);
    lo = __float2bfloat16(v - __bfloat162float(hi));
}
__device__ __forceinline__ void ldsm4(uint32_t* d, uint32_t addr) {
    asm volatile("ldmatrix.sync.aligned.m8n8.x4.shared.b16 {%0,%1,%2,%3}, [%4];"
                 : "=r"(d[0]), "=r"(d[1]), "=r"(d[2]), "=r"(d[3]) : "r"(addr));
}
__device__ __forceinline__ void mma16816(float* c, const uint32_t* a, uint32_t b0, uint32_t b1) {
    asm volatile(
        "mma.sync.aligned.m16n8k16.row.col.f32.bf16.bf16.f32 "
        "{%0,%1,%2,%3}, {%4,%5,%6,%7}, {%8,%9}, {%0,%1,%2,%3};"
        : "+f"(c[0]), "+f"(c[1]), "+f"(c[2]), "+f"(c[3])
        : "r"(a[0]), "r"(a[1]), "r"(a[2]), "r"(a[3]), "r"(b0), "r"(b1));
}

// ===========================================================================
// gemm_mma: split-bf16 GEMM (used for EMBPROJ and FH). Unchanged from R4.
// ===========================================================================
__global__ __launch_bounds__(128) void gemm_mma(
    const __nv_bfloat16* __restrict__ Ahi, const __nv_bfloat16* __restrict__ Alo,
    int maxRow,
    const __nv_bfloat16* __restrict__ Bhi, const __nv_bfloat16* __restrict__ Blo,
    const float* __restrict__ bias, float* __restrict__ C, int Ntot)
{
    extern __shared__ char sm[];
    const int tid = threadIdx.x, lane = tid & 31, wid = tid >> 5;
    const int rowBase = blockIdx.y * 64, colBase = blockIdx.x * 64;
    const int AHI = 0, ALO = 17408, BHI = 34816, BLO = 52224;

#pragma unroll
    for (int p = 0; p < 8; ++p) {
        int idx = p * 128 + tid;
        int r = idx >> 4, ch = idx & 15;
        int rg = min(rowBase + r, maxRow);
        const float4* srch = (const float4*)(Ahi + (size_t)rg * 128);
        const float4* srcl = (const float4*)(Alo + (size_t)rg * 128);
        *(float4*)(sm + AHI + r * 272 + ch * 16) = srch[ch];
        *(float4*)(sm + ALO + r * 272 + ch * 16) = srcl[ch];
    }
#pragma unroll
    for (int p = 0; p < 8; ++p) {
        int idx = p * 128 + tid;
        int r = idx >> 4, ch = idx & 15;
        const float4* srch = (const float4*)(Bhi + (size_t)(colBase + r) * 128);
        const float4* srcl = (const float4*)(Blo + (size_t)(colBase + r) * 128);
        *(float4*)(sm + BHI + r * 272 + ch * 16) = srch[ch];
        *(float4*)(sm + BLO + r * 272 + ch * 16) = srcl[ch];
    }
    __syncthreads();

    const uint32_t sbase = smem_u32(sm);
    const uint32_t aoff_lane = (uint32_t)(lane & 15) * 272 + (uint32_t)(lane >> 4) * 16;
    const uint32_t boff_lane =
        (uint32_t)(wid * 16 + ((lane >> 4) & 1) * 8 + (lane & 7)) * 272 +
        (uint32_t)((lane >> 3) & 1) * 16;

    float acc[4][2][4];
#pragma unroll
    for (int mi = 0; mi < 4; ++mi)
#pragma unroll
        for (int ns = 0; ns < 2; ++ns)
#pragma unroll
            for (int q = 0; q < 4; ++q) acc[mi][ns][q] = 0.f;

#pragma unroll
    for (int pass = 0; pass < 3; ++pass) {
        const uint32_t ab = sbase + (pass == 2 ? ALO : AHI);
        const uint32_t bb = sbase + (pass == 1 ? BLO : BHI);
#pragma unroll
        for (int ks = 0; ks < 8; ++ks) {
            uint32_t b[4];
            ldsm4(b, bb + boff_lane + ks * 32);
#pragma unroll
            for (int mi = 0; mi < 4; ++mi) {
                uint32_t a[4];
                ldsm4(a, ab + aoff_lane + (uint32_t)mi * (16 * 272) + ks * 32);
                mma16816(acc[mi][0], a, b[0], b[1]);
                mma16816(acc[mi][1], a, b[2], b[3]);
            }
        }
    }

    const int er = lane >> 2, ec = (lane & 3) * 2;
#pragma unroll
    for (int mi = 0; mi < 4; ++mi) {
#pragma unroll
        for (int ns = 0; ns < 2; ++ns) {
            int row = rowBase + mi * 16 + er;
            int col = colBase + wid * 16 + ns * 8 + ec;
            float b0 = 0.f, b1 = 0.f;
            if (bias) { b0 = bias[col]; b1 = bias[col + 1]; }
            float2 v0 = make_float2(acc[mi][ns][0] + b0, acc[mi][ns][1] + b1);
            float2 v1 = make_float2(acc[mi][ns][2] + b0, acc[mi][ns][3] + b1);
            *(float2*)&C[(size_t)row * Ntot + col] = v0;
            *(float2*)&C[(size_t)(row + 8) * Ntot + col] = v1;
        }
    }
}

// ===========================================================================
// fused_level: per non-leaf level, one block = 64 parents.
//   phase 1: A = split(sum of children h) in smem  (the hsum)
//   phase 2: HG = A @ Wh^T (384 cols, Wh hi then lo resident in smem)
//   phase 3: hg tile -> smem, full LSTM gate math, write h (bf16 pair) + c
// 512 threads = 16 warps; warp w covers cols [w%8 *48 ...), rows split by w/8.
// Actually: warp tile = 32 rows x 48 cols; warps (w>>3) pick row half,
// (w&7) picks col group of 48.
// ===========================================================================
__global__ __launch_bounds__(512) void fused_level(
    const __nv_bfloat16* __restrict__ hhiC, const __nv_bfloat16* __restrict__ hloC,
    const float* __restrict__ cprev, const float* __restrict__ fh,
    const int* __restrict__ sen, long senOff,
    const float* __restrict__ embproj,
    const __nv_bfloat16* __restrict__ whhi, const __nv_bfloat16* __restrict__ whlo,
    __nv_bfloat16* __restrict__ hhiO, __nv_bfloat16* __restrict__ hloO,
    float* __restrict__ cout, int ratio)
{
    extern __shared__ char sm[];
    const int tid = threadIdx.x, lane = tid & 31, w = tid >> 5;
    const int rowHalf = w >> 3;        // 0/1: rows 0-31 or 32-63
    const int colGrp = w & 7;          // 0..7: cols colGrp*48 .. +48
    const int pBase = blockIdx.x * 64;
    const int AHI = 0, ALO = 17408, BOFF = 34816;   // A: 64x272B each; B: 384x272B

    // ---- phase 1: hsum -> split -> A smem (64 rows x 128 bf16, stride 272B)
#pragma unroll
    for (int it = 0; it < 4; ++it) {
        int t = it * 512 + tid;               // 0..2047
        int p = t >> 5, ch = t & 31;          // parent row, 8B chunk (4 bf16)
        size_t cbase = ((size_t)(pBase + p) * ratio) * 128 + ch * 4;
        float s0 = 0.f, s1 = 0.f, s2 = 0.f, s3 = 0.f;
        for (int r = 0; r < ratio; ++r) {
            uint2 vh = *(const uint2*)(hhiC + cbase + (size_t)r * 128);
            uint2 vl = *(const uint2*)(hloC + cbase + (size_t)r * 128);
            __nv_bfloat162 h01 = *(__nv_bfloat162*)&vh.x, h23 = *(__nv_bfloat162*)&vh.y;
            __nv_bfloat162 l01 = *(__nv_bfloat162*)&vl.x, l23 = *(__nv_bfloat162*)&vl.y;
            float2 fh01 = __bfloat1622float2(h01), fh23 = __bfloat1622float2(h23);
            float2 fl01 = __bfloat1622float2(l01), fl23 = __bfloat1622float2(l23);
            s0 += fh01.x + fl01.x; s1 += fh01.y + fl01.y;
            s2 += fh23.x + fl23.x; s3 += fh23.y + fl23.y;
        }
        __nv_bfloat16 a0, b0, a1, b1, a2, b2, a3, b3;
        split2(s0, a0, b0); split2(s1, a1, b1); split2(s2, a2, b2); split2(s3, a3, b3);
        uint2 vh, vl;
        __nv_bfloat162 tt;
        tt = __nv_bfloat162(a0, a1); vh.x = *(uint32_t*)&tt;
        tt = __nv_bfloat162(a2, a3); vh.y = *(uint32_t*)&tt;
        tt = __nv_bfloat162(b0, b1); vl.x = *(uint32_t*)&tt;
        tt = __nv_bfloat162(b2, b3); vl.y = *(uint32_t*)&tt;
        *(uint2*)(sm + AHI + p * 272 + ch * 8) = vh;
        *(uint2*)(sm + ALO + p * 272 + ch * 8) = vl;
    }
    // ---- load B = Wh_hi (384 x 128 bf16, [n][k])
#pragma unroll
    for (int it = 0; it < 12; ++it) {
        int t = it * 512 + tid;               // 0..6143
        int r = t >> 4, ch = t & 15;
        *(float4*)(sm + BOFF + r * 272 + ch * 16) =
            ((const float4*)(whhi + (size_t)r * 128))[ch];
    }
    __syncthreads();

    const uint32_t sbase = smem_u32(sm);
    const uint32_t aoff = (uint32_t)(lane & 15) * 272 + (uint32_t)(lane >> 4) * 16 +
                          (uint32_t)rowHalf * (32 * 272);
    const uint32_t boff = (uint32_t)(((lane >> 4) & 1) * 8 + (lane & 7)) * 272 +
                          (uint32_t)((lane >> 3) & 1) * 16;

    float acc[2][6][4];
#pragma unroll
    for (int mi = 0; mi < 2; ++mi)
#pragma unroll
        for (int ns = 0; ns < 6; ++ns)
#pragma unroll
            for (int q = 0; q < 4; ++q) acc[mi][ns][q] = 0.f;

    // ---- passes 1&2: Ahi*Bhi, Alo*Bhi
#pragma unroll
    for (int pass = 0; pass < 2; ++pass) {
        const uint32_t ab = sbase + (pass ? ALO : AHI);
#pragma unroll
        for (int ks = 0; ks < 8; ++ks) {
            uint32_t b[3][4];
#pragma unroll
            for (int q = 0; q < 3; ++q)
                ldsm4(b[q], sbase + BOFF + boff + (uint32_t)(colGrp * 48 + q * 16) * 272 + ks * 32);
#pragma unroll
            for (int mi = 0; mi < 2; ++mi) {
                uint32_t a[4];
                ldsm4(a, ab + aoff + (uint32_t)mi * (16 * 272) + ks * 32);
#pragma unroll
                for (int q = 0; q < 3; ++q) {
                    mma16816(acc[mi][2 * q], a, b[q][0], b[q][1]);
                    mma16816(acc[mi][2 * q + 1], a, b[q][2], b[q][3]);
                }
            }
        }
    }
    __syncthreads();
    // ---- reload B = Wh_lo, pass 3: Ahi*Blo
#pragma unroll
    for (int it = 0; it < 12; ++it) {
        int t = it * 512 + tid;
        int r = t >> 4, ch = t & 15;
        *(float4*)(sm + BOFF + r * 272 + ch * 16) =
            ((const float4*)(whlo + (size_t)r * 128))[ch];
    }
    __syncthreads();
#pragma unroll
    for (int ks = 0; ks < 8; ++ks) {
        uint32_t b[3][4];
#pragma unroll
        for (int q = 0; q < 3; ++q)
            ldsm4(b[q], sbase + BOFF + boff + (uint32_t)(colGrp * 48 + q * 16) * 272 + ks * 32);
#pragma unroll
        for (int mi = 0; mi < 2; ++mi) {
            uint32_t a[4];
            ldsm4(a, sbase + AHI + aoff + (uint32_t)mi * (16 * 272) + ks * 32);
#pragma unroll
            for (int q = 0; q < 3; ++q) {
                mma16816(acc[mi][2 * q], a, b[q][0], b[q][1]);
                mma16816(acc[mi][2 * q + 1], a, b[q][2], b[q][3]);
            }
        }
    }
    __syncthreads();

    // ---- stage hg tile to smem (reuse B region): 64 rows x 392-float stride
    float* hgs = (float*)(sm + BOFF);
    const int er = lane >> 2, ec = (lane & 3) * 2;
#pragma unroll
    for (int mi = 0; mi < 2; ++mi) {
#pragma unroll
        for (int ns = 0; ns < 6; ++ns) {
            int row = rowHalf * 32 + mi * 16 + er;
            int col = colGrp * 48 + ns * 8 + ec;
            hgs[row * 392 + col]     = acc[mi][ns][0];
            hgs[row * 392 + col + 1] = acc[mi][ns][1];
            hgs[(row + 8) * 392 + col]     = acc[mi][ns][2];
            hgs[(row + 8) * 392 + col + 1] = acc[mi][ns][3];
        }
    }
    __syncthreads();

    // ---- gate phase: full LSTM cell per (parent, 4-col chunk)
#pragma unroll
    for (int it = 0; it < 4; ++it) {
        int t = it * 512 + tid;               // 0..2047
        int p = t >> 5, j = (t & 31) * 4;
        int srow = __ldg(&sen[senOff + pBase + p]);
        const float* xr = embproj + (size_t)srow * 512;
        const float* hr = hgs + p * 392;
        float4 pi4 = *(const float4*)(xr + j);
        float4 po4 = *(const float4*)(xr + 128 + j);
        float4 pu4 = *(const float4*)(xr + 256 + j);
        float4 pf4 = *(const float4*)(xr + 384 + j);
        float4 gi = *(const float4*)(hr + j);
        float4 go = *(const float4*)(hr + 128 + j);
        float4 gu = *(const float4*)(hr + 256 + j);
        pi4.x += gi.x; pi4.y += gi.y; pi4.z += gi.z; pi4.w += gi.w;
        po4.x += go.x; po4.y += go.y; po4.z += go.z; po4.w += go.w;
        pu4.x += gu.x; pu4.y += gu.y; pu4.z += gu.z; pu4.w += gu.w;
        float ig0 = sigf(pi4.x), ig1 = sigf(pi4.y), ig2 = sigf(pi4.z), ig3 = sigf(pi4.w);
        float og0 = sigf(po4.x), og1 = sigf(po4.y), og2 = sigf(po4.z), og3 = sigf(po4.w);
        float u0 = tanh_(pu4.x), u1 = tanh_(pu4.y), u2 = tanh_(pu4.z), u3 = tanh_(pu4.w);
        float fc0 = 0.f, fc1 = 0.f, fc2 = 0.f, fc3 = 0.f;
        for (int r = 0; r < ratio; ++r) {
            size_t ci = ((size_t)(pBase + p) * ratio + r) * 128 + j;
            float4 fv = *(const float4*)(fh + ci);
            float4 cv = *(const float4*)(cprev + ci);
            fc0 += sigf(pf4.x + fv.x) * cv.x;
            fc1 += sigf(pf4.y + fv.y) * cv.y;
            fc2 += sigf(pf4.z + fv.z) * cv.z;
            fc3 += sigf(pf4.w + fv.w) * cv.w;
        }
        float c0 = ig0 * u0 + fc0, c1 = ig1 * u1 + fc1;
        float c2 = ig2 * u2 + fc2, c3 = ig3 * u3 + fc3;
        float h0 = og0 * tanh_(c0), h1 = og1 * tanh_(c1);
        float h2 = og2 * tanh_(c2), h3 = og3 * tanh_(c3);
        size_t o = (size_t)(pBase + p) * 128 + j;
        *(float4*)(cout + o) = make_float4(c0, c1, c2, c3);
        __nv_bfloat16 a0, b0, a1, b1, a2, b2, a3, b3;
        split2(h0, a0, b0); split2(h1, a1, b1); split2(h2, a2, b2); split2(h3, a3, b3);
        uint2 vh, vl;
        __nv_bfloat162 tt;
        tt = __nv_bfloat162(a0, a1); vh.x = *(uint32_t*)&tt;
        tt = __nv_bfloat162(a2, a3); vh.y = *(uint32_t*)&tt;
        tt = __nv_bfloat162(b0, b1); vl.x = *(uint32_t*)&tt;
        tt = __nv_bfloat162(b2, b3); vl.y = *(uint32_t*)&tt;
        *(uint2*)(hhiO + o) = vh;
        *(uint2*)(hloO + o) = vl;
    }
}

// ----------------------- prep kernels ---------------------------------------
__global__ void split_emb_kernel(const float* __restrict__ emb,
                                 __nv_bfloat16* __restrict__ hi,
                                 __nv_bfloat16* __restrict__ lo, int n)
{
    int i = blockIdx.x * 256 + threadIdx.x;
    if (i >= n) return;
    split2(emb[i], hi[i], lo[i]);
}

__global__ void prep_w_kernel(const float* __restrict__ W,
                              __nv_bfloat16* __restrict__ hi,
                              __nv_bfloat16* __restrict__ lo)
{
    int i = blockIdx.x * 256 + threadIdx.x;  // 16384
    int n = i >> 7, k = i & 127;
    split2(W[k * 128 + n], hi[i], lo[i]);
}

__global__ void bias_kernel(
    const float* bix, const float* bih, const float* box, const float* boh,
    const float* bux, const float* buh, const float* bfx, const float* bfh,
    float* bias)
{
    int j = threadIdx.x;  // 128
    bias[j]       = bix[j] + bih[j];
    bias[128 + j] = box[j] + boh[j];
    bias[256 + j] = bux[j] + buh[j];
    bias[384 + j] = bfx[j] + bfh[j];
}

// ----------------------- leaf elementwise cell -------------------------------
__global__ __launch_bounds__(256) void ew_kernel(
    const int* __restrict__ sen, long senOff,
    const float* __restrict__ embproj,
    __nv_bfloat16* __restrict__ hhi, __nv_bfloat16* __restrict__ hlo,
    float* __restrict__ cout, int nL)
{
    int idx = blockIdx.x * 256 + threadIdx.x;
    int n = idx >> 5, j = (idx & 31) * 4;
    if (n >= nL) return;
    const float* xr = embproj + (size_t)__ldg(&sen[senOff + n]) * 512;
    float4 pi4 = *(const float4*)(xr + j);
    float4 po4 = *(const float4*)(xr + 128 + j);
    float4 pu4 = *(const float4*)(xr + 256 + j);
    float ig0 = sigf(pi4.x), ig1 = sigf(pi4.y), ig2 = sigf(pi4.z), ig3 = sigf(pi4.w);
    float og0 = sigf(po4.x), og1 = sigf(po4.y), og2 = sigf(po4.z), og3 = sigf(po4.w);
    float u0 = tanh_(pu4.x), u1 = tanh_(pu4.y), u2 = tanh_(pu4.z), u3 = tanh_(pu4.w);
    float c0 = ig0 * u0, c1 = ig1 * u1, c2 = ig2 * u2, c3 = ig3 * u3;
    float h0 = og0 * tanh_(c0), h1 = og1 * tanh_(c1);
    float h2 = og2 * tanh_(c2), h3 = og3 * tanh_(c3);
    size_t o = (size_t)n * 128 + j;
    *(float4*)(cout + o) = make_float4(c0, c1, c2, c3);
    __nv_bfloat16 a0, b0, a1, b1, a2, b2, a3, b3;
    split2(h0, a0, b0); split2(h1, a1, b1); split2(h2, a2, b2); split2(h3, a3, b3);
    uint2 vh, vl;
    __nv_bfloat162 t;
    t = __nv_bfloat162(a0, a1); vh.x = *(uint32_t*)&t;
    t = __nv_bfloat162(a2, a3); vh.y = *(uint32_t*)&t;
    t = __nv_bfloat162(b0, b1); vl.x = *(uint32_t*)&t;
    t = __nv_bfloat162(b2, b3); vl.y = *(uint32_t*)&t;
    *(uint2*)(hhi + o) = vh;
    *(uint2*)(hlo + o) = vl;
}

// ----------------------- output projection -----------------------------------
__global__ __launch_bounds__(256) void out_kernel(
    const __nv_bfloat16* __restrict__ hhi, const __nv_bfloat16* __restrict__ hlo,
    const float* __restrict__ Wout, const float* __restrict__ bout,
    float* __restrict__ out)
{
    int g = blockIdx.x * blockDim.x + threadIdx.x;
    int warp = g >> 5, lane = g & 31;
    if (warp >= 4096) return;
    size_t base = (size_t)warp * 128;
    float a0 = 0.f, a1 = 0.f, a2 = 0.f, a3 = 0.f;
    for (int k = lane; k < 128; k += 32) {
        float hv = __bfloat162float(hhi[base + k]) + __bfloat162float(hlo[base + k]);
        const float* wr = Wout + k * 4;
        a0 += hv * wr[0]; a1 += hv * wr[1];
        a2 += hv * wr[2]; a3 += hv * wr[3];
    }
#pragma unroll
    for (int s = 16; s; s >>= 1) {
        a0 += __shfl_xor_sync(0xffffffffu, a0, s);
        a1 += __shfl_xor_sync(0xffffffffu, a1, s);
        a2 += __shfl_xor_sync(0xffffffffu, a2, s);
        a3 += __shfl_xor_sync(0xffffffffu, a3, s);
    }
    if (lane == 0) {
        out[warp * 4 + 0] = a0 + bout[0];
        out[warp * 4 + 1] = a1 + bout[1];
        out[warp * 4 + 2] = a2 + bout[2];
        out[warp * 4 + 3] = a3 + bout[3];
    }
}

// ===========================================================================
extern "C" void kernel_launch(void* const* d_in, const int* in_sizes, int n_in,
                              void* d_out, int out_size)
{
    const int*   sen  = (const int*)d_in[0];
    const float* emb  = (const float*)d_in[1];
    const float* W_ix = (const float*)d_in[2];
    const float* b_ix = (const float*)d_in[3];
    const float* W_ih = (const float*)d_in[4];
    const float* b_ih = (const float*)d_in[5];
    const float* W_fx = (const float*)d_in[6];
    const float* b_fx = (const float*)d_in[7];
    const float* W_fh = (const float*)d_in[8];
    const float* b_fh = (const float*)d_in[9];
    const float* W_ox = (const float*)d_in[10];
    const float* b_ox = (const float*)d_in[11];
    const float* W_oh = (const float*)d_in[12];
    const float* b_oh = (const float*)d_in[13];
    const float* W_ux = (const float*)d_in[14];
    const float* b_ux = (const float*)d_in[15];
    const float* W_uh = (const float*)d_in[16];
    const float* b_uh = (const float*)d_in[17];
    const float* W_out = (const float*)d_in[18];
    const float* b_out = (const float*)d_in[19];
    float* out = (float*)d_out;

    float *embproj, *fh, *c0, *c1, *bias;
    __nv_bfloat16 *h_hi0, *h_lo0, *h_hi1, *h_lo1;
    __nv_bfloat16 *emb_hi, *emb_lo, *wx_hi, *wx_lo, *wh_hi, *wh_lo, *wf_hi, *wf_lo;
    cudaGetSymbolAddress((void**)&embproj, g_embproj);
    cudaGetSymbolAddress((void**)&fh, g_fh);
    cudaGetSymbolAddress((void**)&h_hi0, g_h_hi0);
    cudaGetSymbolAddress((void**)&h_lo0, g_h_lo0);
    cudaGetSymbolAddress((void**)&h_hi1, g_h_hi1);
    cudaGetSymbolAddress((void**)&h_lo1, g_h_lo1);
    cudaGetSymbolAddress((void**)&c0, g_c0);
    cudaGetSymbolAddress((void**)&c1, g_c1);
    cudaGetSymbolAddress((void**)&emb_hi, g_emb_hi);
    cudaGetSymbolAddress((void**)&emb_lo, g_emb_lo);
    cudaGetSymbolAddress((void**)&wx_hi, g_wx_hi);
    cudaGetSymbolAddress((void**)&wx_lo, g_wx_lo);
    cudaGetSymbolAddress((void**)&wh_hi, g_wh_hi);
    cudaGetSymbolAddress((void**)&wh_lo, g_wh_lo);
    cudaGetSymbolAddress((void**)&wf_hi, g_wf_hi);
    cudaGetSymbolAddress((void**)&wf_lo, g_wf_lo);
    cudaGetSymbolAddress((void**)&bias, g_bias);

    const int SMEM_GEMM = 69632;
    const int SMEM_FUSED = 34816 + 104448;  // A(hi+lo) + B/hgs region = 139264
    cudaFuncSetAttribute(gemm_mma, cudaFuncAttributeMaxDynamicSharedMemorySize, SMEM_GEMM);
    cudaFuncSetAttribute(fused_level, cudaFuncAttributeMaxDynamicSharedMemorySize, SMEM_FUSED);

    const int LS[6] = {4096, 16384, 65536, 131072, 262144, 262144};
    long OFFS[7];
    OFFS[0] = 0;
    for (int i = 0; i < 6; ++i) OFFS[i + 1] = OFFS[i] + LS[i];

    __nv_bfloat16* hbufh[2] = {h_hi0, h_hi1};
    __nv_bfloat16* hbufl[2] = {h_lo0, h_lo1};
    float* cbuf[2] = {c0, c1};

    // -------- prep --------
    split_emb_kernel<<<(VOCAB_C * 128 + 255) / 256, 256>>>(emb, emb_hi, emb_lo, VOCAB_C * 128);
    prep_w_kernel<<<64, 256>>>(W_ix, wx_hi + 0 * 16384, wx_lo + 0 * 16384);
    prep_w_kernel<<<64, 256>>>(W_ox, wx_hi + 1 * 16384, wx_lo + 1 * 16384);
    prep_w_kernel<<<64, 256>>>(W_ux, wx_hi + 2 * 16384, wx_lo + 2 * 16384);
    prep_w_kernel<<<64, 256>>>(W_fx, wx_hi + 3 * 16384, wx_lo + 3 * 16384);
    prep_w_kernel<<<64, 256>>>(W_ih, wh_hi + 0 * 16384, wh_lo + 0 * 16384);
    prep_w_kernel<<<64, 256>>>(W_oh, wh_hi + 1 * 16384, wh_lo + 1 * 16384);
    prep_w_kernel<<<64, 256>>>(W_uh, wh_hi + 2 * 16384, wh_lo + 2 * 16384);
    prep_w_kernel<<<64, 256>>>(W_fh, wf_hi, wf_lo);
    bias_kernel<<<1, 128>>>(b_ix, b_ih, b_ox, b_oh, b_ux, b_uh, b_fx, b_fh, bias);

    // -------- EMBPROJ = emb @ [Wx...] + bias, once for the whole vocab -------
    {
        dim3 g(8, VOCAB_PAD_C / 64);
        gemm_mma<<<g, 128, SMEM_GEMM>>>(emb_hi, emb_lo, VOCAB_C - 1,
                                        wx_hi, wx_lo, bias, embproj, 512);
    }

    // -------- bottom-up levels ----------------------------------------------
    int cur = 0;
    int rootBuf = 0;
    for (int L = 5; L >= 0; --L) {
        int nL = LS[L];
        if (L == 5) {
            ew_kernel<<<nL / 8, 256>>>(sen, OFFS[L], embproj,
                                       hbufh[cur], hbufl[cur], cbuf[cur], nL);
        } else {
            int ratio = LS[L + 1] / nL;
            int nc = LS[L + 1];
            int prev = cur ^ 1;
            {
                dim3 g(2, nc / 64);
                gemm_mma<<<g, 128, SMEM_GEMM>>>(hbufh[prev], hbufl[prev], nc - 1,
                                                wf_hi, wf_lo, nullptr, fh, 128);
            }
            fused_level<<<nL / 64, 512, SMEM_FUSED>>>(
                hbufh[prev], hbufl[prev], cbuf[prev], fh,
                sen, OFFS[L], embproj,
                wh_hi, wh_lo,
                hbufh[cur], hbufl[cur], cbuf[cur], ratio);
        }
        if (L == 0) rootBuf = cur;
        cur ^= 1;
    }

    // -------- output projection ---------------------------------------------
    out_kernel<<<(4096 * 32) / 256, 256>>>(hbufh[rootBuf], hbufl[rootBuf],
                                           W_out, b_out, out);
}

// round 10
// speedup vs baseline: 1.2820x; 1.2820x over previous
#include <cuda_runtime.h>
#include <cuda_bf16.h>
#include <cstdint>
#include <cstddef>

// ---------------------------------------------------------------------------
// BatchChildSumTreeLSTM on GB300 — round 9: one fully-fused kernel per level
//   EMBPROJ[50048,512] = emb @ [W_ix|W_ox|W_ux|W_fx] + combined bias (once)
//   per non-leaf level (single kernel, templated on RATIO):
//     load child h (hi/lo) tile -> smem
//     FH = child_h @ W_fh   (MMA, staged to smem, never hits DRAM)
//     HSUM = segsum(child h) (from smem; skipped for RATIO==1)
//     HG = HSUM @ [W_ih|W_oh|W_uh]  (MMA, staged to smem)
//     full LSTM gate math in-block; write h (bf16 pair) + c (fp32)
//   leaf level: ew_kernel (gather EMBPROJ only)
//   Split precision everywhere: bf16 hi+lo, D = Ahi*Bhi + Alo*Bhi + Ahi*Blo.
// ---------------------------------------------------------------------------

#define N_NODES_C 741376
#define VOCAB_C 50000
#define VOCAB_PAD_C 50048   // multiple of 64

// ----------------------- static scratch (no allocs allowed) ----------------
__device__ float g_embproj[(size_t)VOCAB_PAD_C * 512];          // 102.5 MB
__device__ __nv_bfloat16 g_h_hi0[(size_t)262144 * 128];
__device__ __nv_bfloat16 g_h_lo0[(size_t)262144 * 128];
__device__ __nv_bfloat16 g_h_hi1[(size_t)262144 * 128];
__device__ __nv_bfloat16 g_h_lo1[(size_t)262144 * 128];
__device__ float g_c0[(size_t)262144 * 128];
__device__ float g_c1[(size_t)262144 * 128];
__device__ __nv_bfloat16 g_emb_hi[(size_t)VOCAB_C * 128];
__device__ __nv_bfloat16 g_emb_lo[(size_t)VOCAB_C * 128];
__device__ __nv_bfloat16 g_wx_hi[512 * 128], g_wx_lo[512 * 128];  // [n][k]
__device__ __nv_bfloat16 g_wh_hi[384 * 128], g_wh_lo[384 * 128];
__device__ __nv_bfloat16 g_wf_hi[128 * 128], g_wf_lo[128 * 128];
__device__ float g_bias[512];

// ----------------------- helpers --------------------------------------------
__device__ __forceinline__ uint32_t smem_u32(const void* p) {
    uint32_t a;
    asm("{ .reg .u64 t; cvta.to.shared.u64 t, %1; cvt.u32.u64 %0, t; }" : "=r"(a) : "l"(p));
    return a;
}
__device__ __forceinline__ float sigf(float x) { return __fdividef(1.f, 1.f + __expf(-x)); }
__device__ __forceinline__ float tanh_(float x) {
    float a = fabsf(x);
    float e = __expf(-2.f * a);
    float t = (1.f - e) * __fdividef(1.f, 1.f + e);
    return copysignf(t, x);
}
__device__ __forceinline__ void split2(float v, __nv_bfloat16& hi, __nv_bfloat16& lo) {
    hi = __float2bfloat16(v);
    lo = __float2bfloat16(v - __bfloat162float(hi));
}
__device__ __forceinline__ void ldsm4(uint32_t* d, uint32_t addr) {
    asm volatile("ldmatrix.sync.aligned.m8n8.x4.shared.b16 {%0,%1,%2,%3}, [%4];"
                 : "=r"(d[0]), "=r"(d[1]), "=r"(d[2]), "=r"(d[3]) : "r"(addr));
}
__device__ __forceinline__ void mma16816(float* c, const uint32_t* a, uint32_t b0, uint32_t b1) {
    asm volatile(
        "mma.sync.aligned.m16n8k16.row.col.f32.bf16.bf16.f32 "
        "{%0,%1,%2,%3}, {%4,%5,%6,%7}, {%8,%9}, {%0,%1,%2,%3};"
        : "+f"(c[0]), "+f"(c[1]), "+f"(c[2]), "+f"(c[3])
        : "r"(a[0]), "r"(a[1]), "r"(a[2]), "r"(a[3]), "r"(b0), "r"(b1));
}

// ===========================================================================
// gemm_mma: split-bf16 GEMM (EMBPROJ only now). Unchanged from R4.
// ===========================================================================
__global__ __launch_bounds__(128) void gemm_mma(
    const __nv_bfloat16* __restrict__ Ahi, const __nv_bfloat16* __restrict__ Alo,
    int maxRow,
    const __nv_bfloat16* __restrict__ Bhi, const __nv_bfloat16* __restrict__ Blo,
    const float* __restrict__ bias, float* __restrict__ C, int Ntot)
{
    extern __shared__ char sm[];
    const int tid = threadIdx.x, lane = tid & 31, wid = tid >> 5;
    const int rowBase = blockIdx.y * 64, colBase = blockIdx.x * 64;
    const int AHI = 0, ALO = 17408, BHI = 34816, BLO = 52224;

#pragma unroll
    for (int p = 0; p < 8; ++p) {
        int idx = p * 128 + tid;
        int r = idx >> 4, ch = idx & 15;
        int rg = min(rowBase + r, maxRow);
        const float4* srch = (const float4*)(Ahi + (size_t)rg * 128);
        const float4* srcl = (const float4*)(Alo + (size_t)rg * 128);
        *(float4*)(sm + AHI + r * 272 + ch * 16) = srch[ch];
        *(float4*)(sm + ALO + r * 272 + ch * 16) = srcl[ch];
    }
#pragma unroll
    for (int p = 0; p < 8; ++p) {
        int idx = p * 128 + tid;
        int r = idx >> 4, ch = idx & 15;
        const float4* srch = (const float4*)(Bhi + (size_t)(colBase + r) * 128);
        const float4* srcl = (const float4*)(Blo + (size_t)(colBase + r) * 128);
        *(float4*)(sm + BHI + r * 272 + ch * 16) = srch[ch];
        *(float4*)(sm + BLO + r * 272 + ch * 16) = srcl[ch];
    }
    __syncthreads();

    const uint32_t sbase = smem_u32(sm);
    const uint32_t aoff_lane = (uint32_t)(lane & 15) * 272 + (uint32_t)(lane >> 4) * 16;
    const uint32_t boff_lane =
        (uint32_t)(wid * 16 + ((lane >> 4) & 1) * 8 + (lane & 7)) * 272 +
        (uint32_t)((lane >> 3) & 1) * 16;

    float acc[4][2][4];
#pragma unroll
    for (int mi = 0; mi < 4; ++mi)
#pragma unroll
        for (int ns = 0; ns < 2; ++ns)
#pragma unroll
            for (int q = 0; q < 4; ++q) acc[mi][ns][q] = 0.f;

#pragma unroll
    for (int pass = 0; pass < 3; ++pass) {
        const uint32_t ab = sbase + (pass == 2 ? ALO : AHI);
        const uint32_t bb = sbase + (pass == 1 ? BLO : BHI);
#pragma unroll
        for (int ks = 0; ks < 8; ++ks) {
            uint32_t b[4];
            ldsm4(b, bb + boff_lane + ks * 32);
#pragma unroll
            for (int mi = 0; mi < 4; ++mi) {
                uint32_t a[4];
                ldsm4(a, ab + aoff_lane + (uint32_t)mi * (16 * 272) + ks * 32);
                mma16816(acc[mi][0], a, b[0], b[1]);
                mma16816(acc[mi][1], a, b[2], b[3]);
            }
        }
    }

    const int er = lane >> 2, ec = (lane & 3) * 2;
#pragma unroll
    for (int mi = 0; mi < 4; ++mi) {
#pragma unroll
        for (int ns = 0; ns < 2; ++ns) {
            int row = rowBase + mi * 16 + er;
            int col = colBase + wid * 16 + ns * 8 + ec;
            float b0 = 0.f, b1 = 0.f;
            if (bias) { b0 = bias[col]; b1 = bias[col + 1]; }
            float2 v0 = make_float2(acc[mi][ns][0] + b0, acc[mi][ns][1] + b1);
            float2 v1 = make_float2(acc[mi][ns][2] + b0, acc[mi][ns][3] + b1);
            *(float2*)&C[(size_t)row * Ntot + col] = v0;
            *(float2*)&C[(size_t)(row + 8) * Ntot + col] = v1;
        }
    }
}

// ===========================================================================
// fused_level2<RATIO>: one block = P parents (= C/RATIO children rows).
//   P = 64 for RATIO 1,2 ; P = 32 for RATIO 4.  C = P*RATIO (64 or 128).
// smem map (bytes):
//   CH_HI [0, C*272)              child h hi  (bf16, stride 272)
//   CH_LO [C*272, C*544)          child h lo
//   AUX:
//     RATIO>=2: HS_HI/HS_LO (P*272 each)  hsum split pair
//     RATIO==1: FH stage (C*132*4)        (child tile must stay live for HG)
//   OFF_B: B buffer (384*272) — holds Wf hi+lo, then Wh hi, then Wh lo,
//          finally reused as HG fp32 stage (P*392 floats)
//   FH stage for RATIO>=2 overwrites CH (dead after FH MMA + hsum).
// ===========================================================================
template<int RATIO>
__global__ __launch_bounds__(512) void fused_level2(
    const __nv_bfloat16* __restrict__ hhiC, const __nv_bfloat16* __restrict__ hloC,
    const float* __restrict__ cprev,
    const int* __restrict__ sen, long senOff,
    const float* __restrict__ embproj,
    const __nv_bfloat16* __restrict__ wfhi, const __nv_bfloat16* __restrict__ wflo,
    const __nv_bfloat16* __restrict__ whhi, const __nv_bfloat16* __restrict__ whlo,
    __nv_bfloat16* __restrict__ hhiO, __nv_bfloat16* __restrict__ hloO,
    float* __restrict__ cout)
{
    constexpr int P = (RATIO == 4) ? 32 : 64;
    constexpr int C = P * RATIO;             // 64 or 128
    constexpr int CH_HI = 0;
    constexpr int CH_LO = C * 272;
    constexpr int AUX   = C * 544;
    constexpr int OFF_B = (RATIO == 1) ? (AUX + C * 132 * 4) : (AUX + P * 544);
    constexpr int FHS   = (RATIO == 1) ? AUX : CH_HI;
    constexpr int HS_HI = AUX;               // RATIO>=2 only
    constexpr int HS_LO = AUX + P * 272;

    extern __shared__ char sm[];
    const int tid = threadIdx.x, lane = tid & 31, w = tid >> 5;
    const int pBase = blockIdx.x * P;
    const size_t childBase = (size_t)pBase * RATIO;
    const uint32_t sbase = smem_u32(sm);

    // lane-address pieces shared by all ldmatrix uses
    const uint32_t a_ln = (uint32_t)(lane & 15) * 272 + (uint32_t)(lane >> 4) * 16;
    const uint32_t b_ln = (uint32_t)(((lane >> 4) & 1) * 8 + (lane & 7)) * 272 +
                          (uint32_t)((lane >> 3) & 1) * 16;

    // ---- phase 1: load child h tile (hi+lo) and Wf (hi+lo) ----
#pragma unroll
    for (int it = 0; it < C * 16 / 512; ++it) {
        int t = it * 512 + tid;
        int r = t >> 4, ch = t & 15;
        *(float4*)(sm + CH_HI + r * 272 + ch * 16) =
            ((const float4*)(hhiC + (childBase + r) * 128))[ch];
        *(float4*)(sm + CH_LO + r * 272 + ch * 16) =
            ((const float4*)(hloC + (childBase + r) * 128))[ch];
    }
#pragma unroll
    for (int it = 0; it < 4; ++it) {
        int t = it * 512 + tid;           // 0..2047 : 128 rows x 16 chunks
        int r = t >> 4, ch = t & 15;
        *(float4*)(sm + OFF_B + r * 272 + ch * 16) =
            ((const float4*)(wfhi + (size_t)r * 128))[ch];
        *(float4*)(sm + OFF_B + 34816 + r * 272 + ch * 16) =
            ((const float4*)(wflo + (size_t)r * 128))[ch];
    }
    __syncthreads();

    // ---- phase 2: hsum from smem (RATIO>=2) ----
    if (RATIO >= 2) {
#pragma unroll
        for (int it = 0; it < P * 32 / 512; ++it) {
            int t = it * 512 + tid;
            int p = t >> 5, ch = t & 31;     // 4-bf16 (8B) chunks
            float s0 = 0.f, s1 = 0.f, s2 = 0.f, s3 = 0.f;
#pragma unroll
            for (int r = 0; r < RATIO; ++r) {
                uint2 vh = *(uint2*)(sm + CH_HI + (p * RATIO + r) * 272 + ch * 8);
                uint2 vl = *(uint2*)(sm + CH_LO + (p * RATIO + r) * 272 + ch * 8);
                __nv_bfloat162 h01 = *(__nv_bfloat162*)&vh.x, h23 = *(__nv_bfloat162*)&vh.y;
                __nv_bfloat162 l01 = *(__nv_bfloat162*)&vl.x, l23 = *(__nv_bfloat162*)&vl.y;
                float2 fh01 = __bfloat1622float2(h01), fh23 = __bfloat1622float2(h23);
                float2 fl01 = __bfloat1622float2(l01), fl23 = __bfloat1622float2(l23);
                s0 += fh01.x + fl01.x; s1 += fh01.y + fl01.y;
                s2 += fh23.x + fl23.x; s3 += fh23.y + fl23.y;
            }
            __nv_bfloat16 a0, b0, a1, b1, a2, b2, a3, b3;
            split2(s0, a0, b0); split2(s1, a1, b1);
            split2(s2, a2, b2); split2(s3, a3, b3);
            uint2 vh, vl;
            __nv_bfloat162 tt;
            tt = __nv_bfloat162(a0, a1); vh.x = *(uint32_t*)&tt;
            tt = __nv_bfloat162(a2, a3); vh.y = *(uint32_t*)&tt;
            tt = __nv_bfloat162(b0, b1); vl.x = *(uint32_t*)&tt;
            tt = __nv_bfloat162(b2, b3); vl.y = *(uint32_t*)&tt;
            *(uint2*)(sm + HS_HI + p * 272 + ch * 8) = vh;
            *(uint2*)(sm + HS_LO + p * 272 + ch * 8) = vl;
        }
    }

    // ---- phase 3: FH MMA  (C x 128 = child_h @ Wf^T), 3 passes ----
    constexpr int MW = C / 16;               // warps along M: 8 or 4
    const int mrow = (w % MW) * 16;
    const int nBase = (w / MW) * (8 * MW);    // 64-wide (C=128) or 32-wide (C=64)
    float accf[MW][4];
#pragma unroll
    for (int nb = 0; nb < MW; ++nb)
#pragma unroll
        for (int q = 0; q < 4; ++q) accf[nb][q] = 0.f;

#pragma unroll
    for (int pass = 0; pass < 3; ++pass) {
        const uint32_t ab = sbase + (pass == 1 ? CH_LO : CH_HI);
        const uint32_t bb = sbase + OFF_B + (pass == 2 ? 34816 : 0);
#pragma unroll
        for (int ks = 0; ks < 8; ++ks) {
            uint32_t bfr[MW / 2][4];
#pragma unroll
            for (int q = 0; q < MW / 2; ++q)
                ldsm4(bfr[q], bb + b_ln + (uint32_t)(nBase + q * 16) * 272 + ks * 32);
            uint32_t afr[4];
            ldsm4(afr, ab + a_ln + (uint32_t)mrow * 272 + ks * 32);
#pragma unroll
            for (int q = 0; q < MW / 2; ++q) {
                mma16816(accf[2 * q], afr, bfr[q][0], bfr[q][1]);
                mma16816(accf[2 * q + 1], afr, bfr[q][2], bfr[q][3]);
            }
        }
    }
    __syncthreads();   // FH MMA (and hsum) done with CH + B regions

    // ---- phase 4: stage FH to smem (fp32, stride 132); load Wh_hi ----
    {
        float* fhs = (float*)(sm + FHS);
        const int er = lane >> 2, ec = (lane & 3) * 2;
#pragma unroll
        for (int nb = 0; nb < MW; ++nb) {
            int col = nBase + nb * 8 + ec;
            fhs[(mrow + er) * 132 + col]     = accf[nb][0];
            fhs[(mrow + er) * 132 + col + 1] = accf[nb][1];
            fhs[(mrow + er + 8) * 132 + col]     = accf[nb][2];
            fhs[(mrow + er + 8) * 132 + col + 1] = accf[nb][3];
        }
    }
#pragma unroll
    for (int it = 0; it < 12; ++it) {
        int t = it * 512 + tid;               // 384 rows x 16 chunks
        int r = t >> 4, ch = t & 15;
        *(float4*)(sm + OFF_B + r * 272 + ch * 16) =
            ((const float4*)(whhi + (size_t)r * 128))[ch];
    }
    __syncthreads();

    // ---- phase 5: HG MMA  (P x 384 = hsum @ Wh^T) ----
    constexpr int AH = (RATIO == 1) ? CH_HI : HS_HI;
    constexpr int AL = (RATIO == 1) ? CH_LO : HS_LO;
    constexpr int MI = P / 32;                // 2 (P=64) or 1 (P=32)
    const int rowB = (w >> 3) * (16 * MI);
    const int colGrp = w & 7;
    float acc[MI][6][4];
#pragma unroll
    for (int mi = 0; mi < MI; ++mi)
#pragma unroll
        for (int ns = 0; ns < 6; ++ns)
#pragma unroll
            for (int q = 0; q < 4; ++q) acc[mi][ns][q] = 0.f;

#pragma unroll
    for (int pass = 0; pass < 2; ++pass) {    // Ahi*Whhi, Alo*Whhi
        const uint32_t ab = sbase + (pass ? AL : AH);
#pragma unroll
        for (int ks = 0; ks < 8; ++ks) {
            uint32_t bq[3][4];
#pragma unroll
            for (int q = 0; q < 3; ++q)
                ldsm4(bq[q], sbase + OFF_B + b_ln + (uint32_t)(colGrp * 48 + q * 16) * 272 + ks * 32);
#pragma unroll
            for (int mi = 0; mi < MI; ++mi) {
                uint32_t afr[4];
                ldsm4(afr, ab + a_ln + (uint32_t)(rowB + mi * 16) * 272 + ks * 32);
#pragma unroll
                for (int q = 0; q < 3; ++q) {
                    mma16816(acc[mi][2 * q], afr, bq[q][0], bq[q][1]);
                    mma16816(acc[mi][2 * q + 1], afr, bq[q][2], bq[q][3]);
                }
            }
        }
    }
    __syncthreads();
#pragma unroll
    for (int it = 0; it < 12; ++it) {         // load Wh_lo
        int t = it * 512 + tid;
        int r = t >> 4, ch = t & 15;
        *(float4*)(sm + OFF_B + r * 272 + ch * 16) =
            ((const float4*)(whlo + (size_t)r * 128))[ch];
    }
    __syncthreads();
#pragma unroll
    for (int ks = 0; ks < 8; ++ks) {          // pass 3: Ahi*Whlo
        uint32_t bq[3][4];
#pragma unroll
        for (int q = 0; q < 3; ++q)
            ldsm4(bq[q], sbase + OFF_B + b_ln + (uint32_t)(colGrp * 48 + q * 16) * 272 + ks * 32);
#pragma unroll
        for (int mi = 0; mi < MI; ++mi) {
            uint32_t afr[4];
            ldsm4(afr, sbase + AH + a_ln + (uint32_t)(rowB + mi * 16) * 272 + ks * 32);
#pragma unroll
            for (int q = 0; q < 3; ++q) {
                mma16816(acc[mi][2 * q], afr, bq[q][0], bq[q][1]);
                mma16816(acc[mi][2 * q + 1], afr, bq[q][2], bq[q][3]);
            }
        }
    }
    __syncthreads();

    // ---- phase 6: stage HG to smem (B region, stride 392 floats) ----
    {
        float* hgs = (float*)(sm + OFF_B);
        const int er = lane >> 2, ec = (lane & 3) * 2;
#pragma unroll
        for (int mi = 0; mi < MI; ++mi) {
#pragma unroll
            for (int ns = 0; ns < 6; ++ns) {
                int row = rowB + mi * 16 + er;
                int col = colGrp * 48 + ns * 8 + ec;
                hgs[row * 392 + col]     = acc[mi][ns][0];
                hgs[row * 392 + col + 1] = acc[mi][ns][1];
                hgs[(row + 8) * 392 + col]     = acc[mi][ns][2];
                hgs[(row + 8) * 392 + col + 1] = acc[mi][ns][3];
            }
        }
    }
    __syncthreads();

    // ---- phase 7: gates ----
    const float* fhs = (const float*)(sm + FHS);
    const float* hgs = (const float*)(sm + OFF_B);
#pragma unroll
    for (int it = 0; it < P * 32 / 512; ++it) {
        int t = it * 512 + tid;
        int p = t >> 5, j = (t & 31) * 4;
        int srow = __ldg(&sen[senOff + pBase + p]);
        const float* xr = embproj + (size_t)srow * 512;
        const float* hr = hgs + p * 392;
        float4 pi4 = *(const float4*)(xr + j);
        float4 po4 = *(const float4*)(xr + 128 + j);
        float4 pu4 = *(const float4*)(xr + 256 + j);
        float4 pf4 = *(const float4*)(xr + 384 + j);
        float4 gi = *(const float4*)(hr + j);
        float4 go = *(const float4*)(hr + 128 + j);
        float4 gu = *(const float4*)(hr + 256 + j);
        pi4.x += gi.x; pi4.y += gi.y; pi4.z += gi.z; pi4.w += gi.w;
        po4.x += go.x; po4.y += go.y; po4.z += go.z; po4.w += go.w;
        pu4.x += gu.x; pu4.y += gu.y; pu4.z += gu.z; pu4.w += gu.w;
        float ig0 = sigf(pi4.x), ig1 = sigf(pi4.y), ig2 = sigf(pi4.z), ig3 = sigf(pi4.w);
        float og0 = sigf(po4.x), og1 = sigf(po4.y), og2 = sigf(po4.z), og3 = sigf(po4.w);
        float u0 = tanh_(pu4.x), u1 = tanh_(pu4.y), u2 = tanh_(pu4.z), u3 = tanh_(pu4.w);
        float fc0 = 0.f, fc1 = 0.f, fc2 = 0.f, fc3 = 0.f;
#pragma unroll
        for (int r = 0; r < RATIO; ++r) {
            float4 fv = *(const float4*)(fhs + (p * RATIO + r) * 132 + j);
            float4 cv = *(const float4*)(cprev + ((size_t)(pBase + p) * RATIO + r) * 128 + j);
            fc0 += sigf(pf4.x + fv.x) * cv.x;
            fc1 += sigf(pf4.y + fv.y) * cv.y;
            fc2 += sigf(pf4.z + fv.z) * cv.z;
            fc3 += sigf(pf4.w + fv.w) * cv.w;
        }
        float c0 = ig0 * u0 + fc0, c1 = ig1 * u1 + fc1;
        float c2 = ig2 * u2 + fc2, c3 = ig3 * u3 + fc3;
        float h0 = og0 * tanh_(c0), h1 = og1 * tanh_(c1);
        float h2 = og2 * tanh_(c2), h3 = og3 * tanh_(c3);
        size_t o = (size_t)(pBase + p) * 128 + j;
        *(float4*)(cout + o) = make_float4(c0, c1, c2, c3);
        __nv_bfloat16 a0, b0, a1, b1, a2, b2, a3, b3;
        split2(h0, a0, b0); split2(h1, a1, b1); split2(h2, a2, b2); split2(h3, a3, b3);
        uint2 vh, vl;
        __nv_bfloat162 tt;
        tt = __nv_bfloat162(a0, a1); vh.x = *(uint32_t*)&tt;
        tt = __nv_bfloat162(a2, a3); vh.y = *(uint32_t*)&tt;
        tt = __nv_bfloat162(b0, b1); vl.x = *(uint32_t*)&tt;
        tt = __nv_bfloat162(b2, b3); vl.y = *(uint32_t*)&tt;
        *(uint2*)(hhiO + o) = vh;
        *(uint2*)(hloO + o) = vl;
    }
}

// ----------------------- prep kernels ---------------------------------------
__global__ void split_emb_kernel(const float* __restrict__ emb,
                                 __nv_bfloat16* __restrict__ hi,
                                 __nv_bfloat16* __restrict__ lo, int n)
{
    int i = blockIdx.x * 256 + threadIdx.x;
    if (i >= n) return;
    split2(emb[i], hi[i], lo[i]);
}

__global__ void prep_w_kernel(const float* __restrict__ W,
                              __nv_bfloat16* __restrict__ hi,
                              __nv_bfloat16* __restrict__ lo)
{
    int i = blockIdx.x * 256 + threadIdx.x;  // 16384
    int n = i >> 7, k = i & 127;
    split2(W[k * 128 + n], hi[i], lo[i]);
}

__global__ void bias_kernel(
    const float* bix, const float* bih, const float* box, const float* boh,
    const float* bux, const float* buh, const float* bfx, const float* bfh,
    float* bias)
{
    int j = threadIdx.x;  // 128
    bias[j]       = bix[j] + bih[j];
    bias[128 + j] = box[j] + boh[j];
    bias[256 + j] = bux[j] + buh[j];
    bias[384 + j] = bfx[j] + bfh[j];
}

// ----------------------- leaf elementwise cell -------------------------------
__global__ __launch_bounds__(256) void ew_kernel(
    const int* __restrict__ sen, long senOff,
    const float* __restrict__ embproj,
    __nv_bfloat16* __restrict__ hhi, __nv_bfloat16* __restrict__ hlo,
    float* __restrict__ cout, int nL)
{
    int idx = blockIdx.x * 256 + threadIdx.x;
    int n = idx >> 5, j = (idx & 31) * 4;
    if (n >= nL) return;
    const float* xr = embproj + (size_t)__ldg(&sen[senOff + n]) * 512;
    float4 pi4 = *(const float4*)(xr + j);
    float4 po4 = *(const float4*)(xr + 128 + j);
    float4 pu4 = *(const float4*)(xr + 256 + j);
    float ig0 = sigf(pi4.x), ig1 = sigf(pi4.y), ig2 = sigf(pi4.z), ig3 = sigf(pi4.w);
    float og0 = sigf(po4.x), og1 = sigf(po4.y), og2 = sigf(po4.z), og3 = sigf(po4.w);
    float u0 = tanh_(pu4.x), u1 = tanh_(pu4.y), u2 = tanh_(pu4.z), u3 = tanh_(pu4.w);
    float c0 = ig0 * u0, c1 = ig1 * u1, c2 = ig2 * u2, c3 = ig3 * u3;
    float h0 = og0 * tanh_(c0), h1 = og1 * tanh_(c1);
    float h2 = og2 * tanh_(c2), h3 = og3 * tanh_(c3);
    size_t o = (size_t)n * 128 + j;
    *(float4*)(cout + o) = make_float4(c0, c1, c2, c3);
    __nv_bfloat16 a0, b0, a1, b1, a2, b2, a3, b3;
    split2(h0, a0, b0); split2(h1, a1, b1); split2(h2, a2, b2); split2(h3, a3, b3);
    uint2 vh, vl;
    __nv_bfloat162 t;
    t = __nv_bfloat162(a0, a1); vh.x = *(uint32_t*)&t;
    t = __nv_bfloat162(a2, a3); vh.y = *(uint32_t*)&t;
    t = __nv_bfloat162(b0, b1); vl.x = *(uint32_t*)&t;
    t = __nv_bfloat162(b2, b3); vl.y = *(uint32_t*)&t;
    *(uint2*)(hhi + o) = vh;
    *(uint2*)(hlo + o) = vl;
}

// ----------------------- output projection -----------------------------------
__global__ __launch_bounds__(256) void out_kernel(
    const __nv_bfloat16* __restrict__ hhi, const __nv_bfloat16* __restrict__ hlo,
    const float* __restrict__ Wout, const float* __restrict__ bout,
    float* __restrict__ out)
{
    int g = blockIdx.x * blockDim.x + threadIdx.x;
    int warp = g >> 5, lane = g & 31;
    if (warp >= 4096) return;
    size_t base = (size_t)warp * 128;
    float a0 = 0.f, a1 = 0.f, a2 = 0.f, a3 = 0.f;
    for (int k = lane; k < 128; k += 32) {
        float hv = __bfloat162float(hhi[base + k]) + __bfloat162float(hlo[base + k]);
        const float* wr = Wout + k * 4;
        a0 += hv * wr[0]; a1 += hv * wr[1];
        a2 += hv * wr[2]; a3 += hv * wr[3];
    }
#pragma unroll
    for (int s = 16; s; s >>= 1) {
        a0 += __shfl_xor_sync(0xffffffffu, a0, s);
        a1 += __shfl_xor_sync(0xffffffffu, a1, s);
        a2 += __shfl_xor_sync(0xffffffffu, a2, s);
        a3 += __shfl_xor_sync(0xffffffffu, a3, s);
    }
    if (lane == 0) {
        out[warp * 4 + 0] = a0 + bout[0];
        out[warp * 4 + 1] = a1 + bout[1];
        out[warp * 4 + 2] = a2 + bout[2];
        out[warp * 4 + 3] = a3 + bout[3];
    }
}

// ===========================================================================
extern "C" void kernel_launch(void* const* d_in, const int* in_sizes, int n_in,
                              void* d_out, int out_size)
{
    const int*   sen  = (const int*)d_in[0];
    const float* emb  = (const float*)d_in[1];
    const float* W_ix = (const float*)d_in[2];
    const float* b_ix = (const float*)d_in[3];
    const float* W_ih = (const float*)d_in[4];
    const float* b_ih = (const float*)d_in[5];
    const float* W_fx = (const float*)d_in[6];
    const float* b_fx = (const float*)d_in[7];
    const float* W_fh = (const float*)d_in[8];
    const float* b_fh = (const float*)d_in[9];
    const float* W_ox = (const float*)d_in[10];
    const float* b_ox = (const float*)d_in[11];
    const float* W_oh = (const float*)d_in[12];
    const float* b_oh = (const float*)d_in[13];
    const float* W_ux = (const float*)d_in[14];
    const float* b_ux = (const float*)d_in[15];
    const float* W_uh = (const float*)d_in[16];
    const float* b_uh = (const float*)d_in[17];
    const float* W_out = (const float*)d_in[18];
    const float* b_out = (const float*)d_in[19];
    float* out = (float*)d_out;

    float *embproj, *c0, *c1, *bias;
    __nv_bfloat16 *h_hi0, *h_lo0, *h_hi1, *h_lo1;
    __nv_bfloat16 *emb_hi, *emb_lo, *wx_hi, *wx_lo, *wh_hi, *wh_lo, *wf_hi, *wf_lo;
    cudaGetSymbolAddress((void**)&embproj, g_embproj);
    cudaGetSymbolAddress((void**)&h_hi0, g_h_hi0);
    cudaGetSymbolAddress((void**)&h_lo0, g_h_lo0);
    cudaGetSymbolAddress((void**)&h_hi1, g_h_hi1);
    cudaGetSymbolAddress((void**)&h_lo1, g_h_lo1);
    cudaGetSymbolAddress((void**)&c0, g_c0);
    cudaGetSymbolAddress((void**)&c1, g_c1);
    cudaGetSymbolAddress((void**)&emb_hi, g_emb_hi);
    cudaGetSymbolAddress((void**)&emb_lo, g_emb_lo);
    cudaGetSymbolAddress((void**)&wx_hi, g_wx_hi);
    cudaGetSymbolAddress((void**)&wx_lo, g_wx_lo);
    cudaGetSymbolAddress((void**)&wh_hi, g_wh_hi);
    cudaGetSymbolAddress((void**)&wh_lo, g_wh_lo);
    cudaGetSymbolAddress((void**)&wf_hi, g_wf_hi);
    cudaGetSymbolAddress((void**)&wf_lo, g_wf_lo);
    cudaGetSymbolAddress((void**)&bias, g_bias);

    const int SMEM_GEMM = 69632;
    const int SMEM_F1 = 64 * 544 + 64 * 132 * 4 + 104448;   // 173056
    const int SMEM_F2 = 128 * 544 + 64 * 544 + 104448;      // 208896
    const int SMEM_F4 = 128 * 544 + 32 * 544 + 104448;      // 191488
    cudaFuncSetAttribute(gemm_mma, cudaFuncAttributeMaxDynamicSharedMemorySize, SMEM_GEMM);
    cudaFuncSetAttribute(fused_level2<1>, cudaFuncAttributeMaxDynamicSharedMemorySize, SMEM_F1);
    cudaFuncSetAttribute(fused_level2<2>, cudaFuncAttributeMaxDynamicSharedMemorySize, SMEM_F2);
    cudaFuncSetAttribute(fused_level2<4>, cudaFuncAttributeMaxDynamicSharedMemorySize, SMEM_F4);

    const int LS[6] = {4096, 16384, 65536, 131072, 262144, 262144};
    long OFFS[7];
    OFFS[0] = 0;
    for (int i = 0; i < 6; ++i) OFFS[i + 1] = OFFS[i] + LS[i];

    __nv_bfloat16* hbufh[2] = {h_hi0, h_hi1};
    __nv_bfloat16* hbufl[2] = {h_lo0, h_lo1};
    float* cbuf[2] = {c0, c1};

    // -------- prep --------
    split_emb_kernel<<<(VOCAB_C * 128 + 255) / 256, 256>>>(emb, emb_hi, emb_lo, VOCAB_C * 128);
    prep_w_kernel<<<64, 256>>>(W_ix, wx_hi + 0 * 16384, wx_lo + 0 * 16384);
    prep_w_kernel<<<64, 256>>>(W_ox, wx_hi + 1 * 16384, wx_lo + 1 * 16384);
    prep_w_kernel<<<64, 256>>>(W_ux, wx_hi + 2 * 16384, wx_lo + 2 * 16384);
    prep_w_kernel<<<64, 256>>>(W_fx, wx_hi + 3 * 16384, wx_lo + 3 * 16384);
    prep_w_kernel<<<64, 256>>>(W_ih, wh_hi + 0 * 16384, wh_lo + 0 * 16384);
    prep_w_kernel<<<64, 256>>>(W_oh, wh_hi + 1 * 16384, wh_lo + 1 * 16384);
    prep_w_kernel<<<64, 256>>>(W_uh, wh_hi + 2 * 16384, wh_lo + 2 * 16384);
    prep_w_kernel<<<64, 256>>>(W_fh, wf_hi, wf_lo);
    bias_kernel<<<1, 128>>>(b_ix, b_ih, b_ox, b_oh, b_ux, b_uh, b_fx, b_fh, bias);

    // -------- EMBPROJ = emb @ [Wx...] + bias, once for the whole vocab -------
    {
        dim3 g(8, VOCAB_PAD_C / 64);
        gemm_mma<<<g, 128, SMEM_GEMM>>>(emb_hi, emb_lo, VOCAB_C - 1,
                                        wx_hi, wx_lo, bias, embproj, 512);
    }

    // -------- bottom-up levels ----------------------------------------------
    int cur = 0;
    int rootBuf = 0;
    for (int L = 5; L >= 0; --L) {
        int nL = LS[L];
        if (L == 5) {
            ew_kernel<<<nL / 8, 256>>>(sen, OFFS[L], embproj,
                                       hbufh[cur], hbufl[cur], cbuf[cur], nL);
        } else {
            int ratio = LS[L + 1] / nL;
            int prev = cur ^ 1;
            if (ratio == 1) {
                fused_level2<1><<<nL / 64, 512, SMEM_F1>>>(
                    hbufh[prev], hbufl[prev], cbuf[prev],
                    sen, OFFS[L], embproj,
                    wf_hi, wf_lo, wh_hi, wh_lo,
                    hbufh[cur], hbufl[cur], cbuf[cur]);
            } else if (ratio == 2) {
                fused_level2<2><<<nL / 64, 512, SMEM_F2>>>(
                    hbufh[prev], hbufl[prev], cbuf[prev],
                    sen, OFFS[L], embproj,
                    wf_hi, wf_lo, wh_hi, wh_lo,
                    hbufh[cur], hbufl[cur], cbuf[cur]);
            } else {
                fused_level2<4><<<nL / 32, 512, SMEM_F4>>>(
                    hbufh[prev], hbufl[prev], cbuf[prev],
                    sen, OFFS[L], embproj,
                    wf_hi, wf_lo, wh_hi, wh_lo,
                    hbufh[cur], hbufl[cur], cbuf[cur]);
            }
        }
        if (L == 0) rootBuf = cur;
        cur ^= 1;
    }

    // -------- output projection ---------------------------------------------
    out_kernel<<<(4096 * 32) / 256, 256>>>(hbufh[rootBuf], hbufl[rootBuf],
                                           W_out, b_out, out);
}